// round 1
// baseline (speedup 1.0000x reference)
#include <cuda_runtime.h>

// ---------------- constants ----------------
// T=1, h0=c0=0  =>  w_hh* unused, f-gate unused.
// Packed weight buffer layout (floats):
//   [0,      6144)  L0:    k in [0,64), j in [0,96):  w_ih0[row(j)][k]      (k*96+j)
//   [6144,  18432)  L1..4: per layer 3072: k in [0,32), j in [0,96)
//   [18432, 20480)  FC:    k in [0,32), j in [0,64):  fc_w[j][k]            (k*64+j)
//   [20480, 20960)  bias:  layer l: 96 combined biases (b_ih+b_hh, i/g/o rows)
//   [20960, 21024)  fc_b:  64
// row(j): j<32 -> j (i gates), 32<=j<64 -> j+32 (g gates), 64<=j<96 -> j+32 (o gates)

#define NT      512
#define ROWP    65
#define WFLOATS 21024
#define SMEM_BYTES ((WFLOATS + NT * ROWP) * 4)

__device__ __align__(16) float g_w[WFLOATS];

// ---------------- fast math helpers ----------------
__device__ __forceinline__ float ex2f(float x) {
    float y; asm("ex2.approx.f32 %0, %1;" : "=f"(y) : "f"(x)); return y;
}
__device__ __forceinline__ float rcpf(float x) {
    float y; asm("rcp.approx.f32 %0, %1;" : "=f"(y) : "f"(x)); return y;
}
__device__ __forceinline__ float sigf(float x) {
    // 1/(1+e^-x) = 1/(1+2^(-x*log2e))
    return rcpf(1.0f + ex2f(-1.4426950408889634f * x));
}
__device__ __forceinline__ float tanhf_(float x) {
    // tanh(x) = 1 - 2/(e^(2x)+1);  e^(2x) = 2^(x*2*log2e)
    return 1.0f - 2.0f * rcpf(1.0f + ex2f(2.8853900817779268f * x));
}

// ---------------- packed f32x2 helpers ----------------
__device__ __forceinline__ unsigned long long ffma2(unsigned long long a,
                                                    unsigned long long b,
                                                    unsigned long long c) {
    unsigned long long d;
    asm("fma.rn.f32x2 %0, %1, %2, %3;" : "=l"(d) : "l"(a), "l"(b), "l"(c));
    return d;
}
__device__ __forceinline__ unsigned long long pack2(float lo, float hi) {
    unsigned long long d;
    asm("mov.b64 %0, {%1, %2};" : "=l"(d) : "f"(lo), "f"(hi));
    return d;
}
__device__ __forceinline__ float2 unpack2(unsigned long long v) {
    float lo, hi;
    asm("mov.b64 {%0, %1}, %2;" : "=f"(lo), "=f"(hi) : "l"(v));
    return make_float2(lo, hi);
}

// ---------------- weight pack kernel ----------------
__global__ void _LSTM_pack_kernel(const float* __restrict__ w_ih0,
                                  const float* __restrict__ w_ih_rest,
                                  const float* __restrict__ b_ih,
                                  const float* __restrict__ b_hh,
                                  const float* __restrict__ fc_w,
                                  const float* __restrict__ fc_b) {
    int i = blockIdx.x * blockDim.x + threadIdx.x;
    if (i >= WFLOATS) return;
    float v;
    if (i < 6144) {                       // layer 0 weights
        int k = i / 96, j = i % 96;
        int r = (j < 32) ? j : j + 32;
        v = w_ih0[r * 64 + k];
    } else if (i < 18432) {               // layers 1..4 weights
        int q = i - 6144;
        int l = q / 3072; q %= 3072;
        int k = q / 96, j = q % 96;
        int r = (j < 32) ? j : j + 32;
        v = w_ih_rest[l * 4096 + r * 32 + k];
    } else if (i < 20480) {               // fc weights
        int q = i - 18432;
        int k = q / 64, j = q % 64;
        v = fc_w[j * 32 + k];
    } else if (i < 20960) {               // combined biases
        int q = i - 20480;
        int l = q / 96, j = q % 96;
        int r = (j < 32) ? j : j + 32;
        v = b_ih[l * 128 + r] + b_hh[l * 128 + r];
    } else {                              // fc bias
        v = fc_b[i - 20960];
    }
    g_w[i] = v;
}

// ---------------- activation: gates -> h (written to own smem row) ----------
__device__ __forceinline__ void activate(const unsigned long long* acc, float* row) {
#pragma unroll
    for (int j = 0; j < 16; j++) {
        float2 iv = unpack2(acc[j]);        // gates 2j, 2j+1 (i block)
        float2 gv = unpack2(acc[16 + j]);   // g block
        float2 ov = unpack2(acc[32 + j]);   // o block
        float c0 = sigf(iv.x) * tanhf_(gv.x);
        float c1 = sigf(iv.y) * tanhf_(gv.y);
        row[2 * j]     = sigf(ov.x) * tanhf_(c0);
        row[2 * j + 1] = sigf(ov.y) * tanhf_(c1);
    }
}

// ---------------- main kernel ----------------
__global__ void __launch_bounds__(NT, 1)
_LSTM_main_kernel(const float* __restrict__ x, float* __restrict__ out, int B) {
    extern __shared__ float smem[];
    float* Wb   = smem;             // 21024 floats: weights + biases
    float* tile = smem + WFLOATS;   // NT rows x 65 floats

    const int tid = threadIdx.x;
    const long long base = (long long)blockIdx.x * NT * 64;
    const long long lim  = (long long)B * 64;

    // cooperative copy of packed weights into smem (vectorized)
#pragma unroll 4
    for (int p = tid; p < WFLOATS / 4; p += NT)
        ((float4*)Wb)[p] = ((const float4*)g_w)[p];

    // coalesced load of x tile into [b_local][k] rows (pitch 65: conflict-free)
    for (int p = tid; p < NT * 64; p += NT) {
        long long g = base + p;
        if (g < lim) tile[(p >> 6) * ROWP + (p & 63)] = x[g];
    }
    __syncthreads();

    float* row = tile + tid * ROWP;   // this thread's private row
    unsigned long long acc[48];       // 96 gate accumulators, packed f32x2

    // ---- layer 0: in_dim = 64 ----
    {
        const unsigned long long* bias = (const unsigned long long*)(Wb + 20480);
#pragma unroll
        for (int j = 0; j < 48; j++) acc[j] = bias[j];
        const float* Wl = Wb;
#pragma unroll 2
        for (int k = 0; k < 64; k++) {
            float xk = row[k];
            unsigned long long xx = pack2(xk, xk);
            const longlong2* w = (const longlong2*)(Wl + k * 96);
#pragma unroll
            for (int j = 0; j < 24; j++) {
                longlong2 wv = w[j];
                acc[2 * j]     = ffma2((unsigned long long)wv.x, xx, acc[2 * j]);
                acc[2 * j + 1] = ffma2((unsigned long long)wv.y, xx, acc[2 * j + 1]);
            }
        }
        activate(acc, row);
    }

    // ---- layers 1..4: in_dim = 32 ----
    for (int l = 0; l < 4; l++) {
        const unsigned long long* bias =
            (const unsigned long long*)(Wb + 20480 + 96 * (l + 1));
#pragma unroll
        for (int j = 0; j < 48; j++) acc[j] = bias[j];
        const float* Wl = Wb + 6144 + l * 3072;
#pragma unroll 2
        for (int k = 0; k < 32; k++) {
            float hk = row[k];
            unsigned long long xx = pack2(hk, hk);
            const longlong2* w = (const longlong2*)(Wl + k * 96);
#pragma unroll
            for (int j = 0; j < 24; j++) {
                longlong2 wv = w[j];
                acc[2 * j]     = ffma2((unsigned long long)wv.x, xx, acc[2 * j]);
                acc[2 * j + 1] = ffma2((unsigned long long)wv.y, xx, acc[2 * j + 1]);
            }
        }
        activate(acc, row);
    }

    // ---- fc: out[64] = h[32] @ fc_w^T + fc_b ----
    {
        unsigned long long o2[32];
        const unsigned long long* fb = (const unsigned long long*)(Wb + 20960);
#pragma unroll
        for (int j = 0; j < 32; j++) o2[j] = fb[j];
        const float* Wf = Wb + 18432;
#pragma unroll 2
        for (int k = 0; k < 32; k++) {
            float hk = row[k];
            unsigned long long xx = pack2(hk, hk);
            const longlong2* w = (const longlong2*)(Wf + k * 64);
#pragma unroll
            for (int j = 0; j < 16; j++) {
                longlong2 wv = w[j];
                o2[2 * j]     = ffma2((unsigned long long)wv.x, xx, o2[2 * j]);
                o2[2 * j + 1] = ffma2((unsigned long long)wv.y, xx, o2[2 * j + 1]);
            }
        }
#pragma unroll
        for (int j = 0; j < 32; j++) {
            float2 v = unpack2(o2[j]);
            row[2 * j]     = v.x;
            row[2 * j + 1] = v.y;
        }
    }
    __syncthreads();

    // coalesced store of the block's output tile
    for (int p = tid; p < NT * 64; p += NT) {
        long long g = base + p;
        if (g < lim) out[g] = tile[(p >> 6) * ROWP + (p & 63)];
    }
}

// ---------------- launch ----------------
extern "C" void kernel_launch(void* const* d_in, const int* in_sizes, int n_in,
                              void* d_out, int out_size) {
    (void)n_in; (void)out_size;
    const float* x         = (const float*)d_in[0];
    const float* w_ih0     = (const float*)d_in[1];
    // d_in[2] = w_hh0      (unused: h0 == 0, T == 1)
    const float* w_ih_rest = (const float*)d_in[3];
    // d_in[4] = w_hh_rest  (unused)
    const float* b_ih      = (const float*)d_in[5];
    const float* b_hh      = (const float*)d_in[6];
    const float* fc_w      = (const float*)d_in[7];
    const float* fc_b      = (const float*)d_in[8];
    float* out = (float*)d_out;

    int B = in_sizes[0] / 64;

    _LSTM_pack_kernel<<<(WFLOATS + 255) / 256, 256>>>(
        w_ih0, w_ih_rest, b_ih, b_hh, fc_w, fc_b);

    cudaFuncSetAttribute(_LSTM_main_kernel,
                         cudaFuncAttributeMaxDynamicSharedMemorySize, SMEM_BYTES);
    int blocks = (B + NT - 1) / NT;
    _LSTM_main_kernel<<<blocks, NT, SMEM_BYTES>>>(x, out, B);
}

// round 2
// speedup vs baseline: 1.1105x; 1.1105x over previous
#include <cuda_runtime.h>

// T=1, h0=c0=0  =>  w_hh* unused, f-gate unused.
// Packed weight buffer layout (floats), identical to R1:
//   [0,      6144)  L0:    k in [0,64), j in [0,96):  w_ih0[row(j)][k]      (k*96+j)
//   [6144,  18432)  L1..4: per layer 3072: k in [0,32), j in [0,96)
//   [18432, 20480)  FC:    k in [0,32), j in [0,64):  fc_w[j][k]            (k*64+j)
//   [20480, 20960)  bias:  layer l: 96 combined biases (b_ih+b_hh, i/g/o rows)
//   [20960, 21024)  fc_b:  64
// row(j): j<32 -> j (i), 32<=j<64 -> j+32 (g), 64<=j<96 -> j+32 (o)

#define NT      256          // threads per block
#define TILE    512          // batch elements per block (2 per thread)
#define ROWP    65           // smem tile pitch (conflict-free scalar row reads)
#define WFLOATS 21024
#define SMEM_BYTES ((WFLOATS + TILE * ROWP) * 4)

__device__ __align__(16) float g_w[WFLOATS];

// ---------------- fast math helpers ----------------
__device__ __forceinline__ float ex2f(float x) {
    float y; asm("ex2.approx.f32 %0, %1;" : "=f"(y) : "f"(x)); return y;
}
__device__ __forceinline__ float rcpf(float x) {
    float y; asm("rcp.approx.f32 %0, %1;" : "=f"(y) : "f"(x)); return y;
}
__device__ __forceinline__ float sigf(float x) {
    return rcpf(1.0f + ex2f(-1.4426950408889634f * x));
}
__device__ __forceinline__ float tanhf_(float x) {
    return 1.0f - 2.0f * rcpf(1.0f + ex2f(2.8853900817779268f * x));
}

// ---------------- packed f32x2 helpers ----------------
__device__ __forceinline__ unsigned long long ffma2(unsigned long long a,
                                                    unsigned long long b,
                                                    unsigned long long c) {
    unsigned long long d;
    asm("fma.rn.f32x2 %0, %1, %2, %3;" : "=l"(d) : "l"(a), "l"(b), "l"(c));
    return d;
}
__device__ __forceinline__ unsigned long long pack2(float lo, float hi) {
    unsigned long long d;
    asm("mov.b64 %0, {%1, %2};" : "=l"(d) : "f"(lo), "f"(hi));
    return d;
}
__device__ __forceinline__ float2 unpack2(unsigned long long v) {
    float lo, hi;
    asm("mov.b64 {%0, %1}, %2;" : "=f"(lo), "=f"(hi) : "l"(v));
    return make_float2(lo, hi);
}

// ---------------- weight pack kernel ----------------
__global__ void _LSTM_pack_kernel(const float* __restrict__ w_ih0,
                                  const float* __restrict__ w_ih_rest,
                                  const float* __restrict__ b_ih,
                                  const float* __restrict__ b_hh,
                                  const float* __restrict__ fc_w,
                                  const float* __restrict__ fc_b) {
    int i = blockIdx.x * blockDim.x + threadIdx.x;
    if (i >= WFLOATS) return;
    float v;
    if (i < 6144) {
        int k = i / 96, j = i % 96;
        int r = (j < 32) ? j : j + 32;
        v = w_ih0[r * 64 + k];
    } else if (i < 18432) {
        int q = i - 6144;
        int l = q / 3072; q %= 3072;
        int k = q / 96, j = q % 96;
        int r = (j < 32) ? j : j + 32;
        v = w_ih_rest[l * 4096 + r * 32 + k];
    } else if (i < 20480) {
        int q = i - 18432;
        int k = q / 64, j = q % 64;
        v = fc_w[j * 32 + k];
    } else if (i < 20960) {
        int q = i - 20480;
        int l = q / 96, j = q % 96;
        int r = (j < 32) ? j : j + 32;
        v = b_ih[l * 128 + r] + b_hh[l * 128 + r];
    } else {
        v = fc_b[i - 20960];
    }
    g_w[i] = v;
}

// -------- one gate-block GEMV pass: 32 outputs x 2 elements --------
// Accumulates a0/a1 (16 packed f32x2 each) over KDIM input values.
template<int KDIM, int PITCH>
__device__ __forceinline__ void pass_accum(
    const float* __restrict__ Wp,          // weights, row k at Wp + k*PITCH
    const float* __restrict__ x0,          // element 0 inputs (KDIM floats)
    const float* __restrict__ x1,          // element 1 inputs
    const unsigned long long* __restrict__ bias,  // 16 packed biases
    unsigned long long* a0, unsigned long long* a1)
{
#pragma unroll
    for (int j = 0; j < 16; j++) { a0[j] = bias[j]; a1[j] = bias[j]; }
#pragma unroll 4
    for (int k = 0; k < KDIM; k++) {
        float v0 = x0[k], v1 = x1[k];
        unsigned long long xx0 = pack2(v0, v0);
        unsigned long long xx1 = pack2(v1, v1);
        const longlong2* w = (const longlong2*)(Wp + k * PITCH);
#pragma unroll
        for (int j = 0; j < 8; j++) {
            longlong2 wv = w[j];
            a0[2 * j]     = ffma2((unsigned long long)wv.x, xx0, a0[2 * j]);
            a1[2 * j]     = ffma2((unsigned long long)wv.x, xx1, a1[2 * j]);
            a0[2 * j + 1] = ffma2((unsigned long long)wv.y, xx0, a0[2 * j + 1]);
            a1[2 * j + 1] = ffma2((unsigned long long)wv.y, xx1, a1[2 * j + 1]);
        }
    }
}

// -------- one LSTM layer for 2 elements: 3 passes (i, g, o) --------
template<int KDIM>
__device__ __forceinline__ void lstm_layer(
    const float* __restrict__ Wl,    // [KDIM][96]
    const float* __restrict__ bias,  // 96 combined biases
    const float* in0, const float* in1,
    float* out0, float* out1)
{
    unsigned long long a0[16], a1[16];
    float c0[32], c1[32];

    // pass I: c = sigma(i)
    pass_accum<KDIM, 96>(Wl, in0, in1, (const unsigned long long*)bias, a0, a1);
#pragma unroll
    for (int j = 0; j < 16; j++) {
        float2 v0 = unpack2(a0[j]), v1 = unpack2(a1[j]);
        c0[2 * j] = sigf(v0.x);  c0[2 * j + 1] = sigf(v0.y);
        c1[2 * j] = sigf(v1.x);  c1[2 * j + 1] = sigf(v1.y);
    }
    // pass G: c *= tanh(g)
    pass_accum<KDIM, 96>(Wl + 32, in0, in1,
                         (const unsigned long long*)(bias + 32), a0, a1);
#pragma unroll
    for (int j = 0; j < 16; j++) {
        float2 v0 = unpack2(a0[j]), v1 = unpack2(a1[j]);
        c0[2 * j]     *= tanhf_(v0.x);  c0[2 * j + 1] *= tanhf_(v0.y);
        c1[2 * j]     *= tanhf_(v1.x);  c1[2 * j + 1] *= tanhf_(v1.y);
    }
    // pass O: h = sigma(o) * tanh(c)
    pass_accum<KDIM, 96>(Wl + 64, in0, in1,
                         (const unsigned long long*)(bias + 64), a0, a1);
#pragma unroll
    for (int j = 0; j < 16; j++) {
        float2 v0 = unpack2(a0[j]), v1 = unpack2(a1[j]);
        out0[2 * j]     = sigf(v0.x) * tanhf_(c0[2 * j]);
        out0[2 * j + 1] = sigf(v0.y) * tanhf_(c0[2 * j + 1]);
        out1[2 * j]     = sigf(v1.x) * tanhf_(c1[2 * j]);
        out1[2 * j + 1] = sigf(v1.y) * tanhf_(c1[2 * j + 1]);
    }
}

// ---------------- main kernel ----------------
__global__ void __launch_bounds__(NT, 1)
_LSTM_main_kernel(const float* __restrict__ x, float* __restrict__ out, int B) {
    extern __shared__ float smem[];
    float* Wb   = smem;             // 21024 floats: weights + biases
    float* tile = smem + WFLOATS;   // TILE rows x 65 floats

    const int tid = threadIdx.x;
    const long long base = (long long)blockIdx.x * TILE * 64;
    const long long lim  = (long long)B * 64;

    // cooperative copy of packed weights into smem (vectorized)
#pragma unroll 4
    for (int p = tid; p < WFLOATS / 4; p += NT)
        ((float4*)Wb)[p] = ((const float4*)g_w)[p];

    // coalesced float4 loads of the x tile; scalar STS (pitch 65 breaks 16B align)
    {
        const float4* x4 = (const float4*)x;
        long long base4 = base >> 2, lim4 = lim >> 2;
#pragma unroll 4
        for (int p = tid; p < TILE * 16; p += NT) {
            long long g4 = base4 + p;
            if (g4 < lim4) {
                float4 v = x4[g4];
                float* dst = tile + (p >> 4) * ROWP + (p & 15) * 4;
                dst[0] = v.x; dst[1] = v.y; dst[2] = v.z; dst[3] = v.w;
            }
        }
    }
    __syncthreads();

    // this thread's two private rows (tid and tid+256: conflict-free, pitch 65)
    float* r0 = tile + tid * ROWP;
    float* r1 = tile + (tid + NT) * ROWP;

    const float* bias0 = Wb + 20480;

    // layer 0: in_dim 64
    lstm_layer<64>(Wb, bias0, r0, r1, r0, r1);
    // layers 1..3: in_dim 32
#pragma unroll 1
    for (int l = 0; l < 3; l++)
        lstm_layer<32>(Wb + 6144 + l * 3072, bias0 + 96 * (l + 1), r0, r1, r0, r1);
    // layer 4: write h at row offset +33 so fc can safely overwrite cols 0..63
    lstm_layer<32>(Wb + 6144 + 3 * 3072, bias0 + 96 * 4, r0, r1, r0 + 33, r1 + 33);

    // fc: out[64] = h[32] @ fc_w^T + fc_b, two passes of 32 outputs
    {
        const float* Wf = Wb + 18432;
        const unsigned long long* fb = (const unsigned long long*)(Wb + 20960);
        unsigned long long a0[16], a1[16];

        pass_accum<32, 64>(Wf, r0 + 33, r1 + 33, fb, a0, a1);
#pragma unroll
        for (int j = 0; j < 16; j++) {
            float2 v0 = unpack2(a0[j]), v1 = unpack2(a1[j]);
            r0[2 * j] = v0.x; r0[2 * j + 1] = v0.y;
            r1[2 * j] = v1.x; r1[2 * j + 1] = v1.y;
        }
        pass_accum<32, 64>(Wf + 32, r0 + 33, r1 + 33, fb + 16, a0, a1);
#pragma unroll
        for (int j = 0; j < 16; j++) {
            float2 v0 = unpack2(a0[j]), v1 = unpack2(a1[j]);
            r0[32 + 2 * j] = v0.x; r0[33 + 2 * j] = v0.y;
            r1[32 + 2 * j] = v1.x; r1[33 + 2 * j] = v1.y;
        }
    }
    __syncthreads();

    // coalesced float4 stores of the block's output tile
    {
        float4* o4 = (float4*)out;
        long long base4 = base >> 2, lim4 = lim >> 2;
#pragma unroll 4
        for (int p = tid; p < TILE * 16; p += NT) {
            long long g4 = base4 + p;
            if (g4 < lim4) {
                const float* src = tile + (p >> 4) * ROWP + (p & 15) * 4;
                float4 v; v.x = src[0]; v.y = src[1]; v.z = src[2]; v.w = src[3];
                o4[g4] = v;
            }
        }
    }
}

// ---------------- launch ----------------
extern "C" void kernel_launch(void* const* d_in, const int* in_sizes, int n_in,
                              void* d_out, int out_size) {
    (void)n_in; (void)out_size;
    const float* x         = (const float*)d_in[0];
    const float* w_ih0     = (const float*)d_in[1];
    // d_in[2] = w_hh0      (unused: h0 == 0, T == 1)
    const float* w_ih_rest = (const float*)d_in[3];
    // d_in[4] = w_hh_rest  (unused)
    const float* b_ih      = (const float*)d_in[5];
    const float* b_hh      = (const float*)d_in[6];
    const float* fc_w      = (const float*)d_in[7];
    const float* fc_b      = (const float*)d_in[8];
    float* out = (float*)d_out;

    int B = in_sizes[0] / 64;

    _LSTM_pack_kernel<<<(WFLOATS + 255) / 256, 256>>>(
        w_ih0, w_ih_rest, b_ih, b_hh, fc_w, fc_b);

    cudaFuncSetAttribute(_LSTM_main_kernel,
                         cudaFuncAttributeMaxDynamicSharedMemorySize, SMEM_BYTES);
    int blocks = (B + TILE - 1) / TILE;
    _LSTM_main_kernel<<<blocks, NT, SMEM_BYTES>>>(x, out, B);
}

// round 4
// speedup vs baseline: 1.7865x; 1.6086x over previous
#include <cuda_runtime.h>
#include <cuda_bf16.h>
#include <cstdint>

// ============================================================================
// T=1, h0=c0=0 => w_hh* unused, f-gate unused. Chain of small GEMMs on the
// HMMA path (mma.sync m16n8k16 bf16 — plain sm_80+ PTX; tcgen05 is blocked by
// the harness's compute_103 virtual arch).
// bf16x3 accuracy: A segments [hi, hi, lo] vs W segments [Whi, Wlo, Whi].
// Weights pre-packed in mma B-fragment register order -> conflict-free LDS.64.
// Persistent: 148 CTAs x 512 threads; warp owns 32 rows (2 m16 tiles),
// warp-private A smem buffer -> no block syncs in the layer chain.
// ============================================================================

#define NT    512
#define GRID  148
#define AP    272                        // A-buffer row pitch (bytes), 16B-mult
#define WIMG  84096                      // 81920B frags + 544*4B biases
#define WARP_ABUF (32 * AP)              // 8704 B
#define SMEM_BYTES (WIMG + 16 * WARP_ABUF)   // 223360

// fragment-image byte bases per stage
#define WB_L0 0
#define WB_L1 24576
#define WB_L2 36864
#define WB_L3 49152
#define WB_L4 61440
#define WB_FC 73728
#define BIAS_OFF 81920

__device__ __align__(16) unsigned char g_img[WIMG];

// ---------------- fast activations ----------------
__device__ __forceinline__ float ex2f(float x) {
    float y; asm("ex2.approx.f32 %0, %1;" : "=f"(y) : "f"(x)); return y;
}
__device__ __forceinline__ float rcpf(float x) {
    float y; asm("rcp.approx.f32 %0, %1;" : "=f"(y) : "f"(x)); return y;
}
__device__ __forceinline__ float sigf(float x) {
    return rcpf(1.0f + ex2f(-1.4426950408889634f * x));
}
__device__ __forceinline__ float tanhf_(float x) {
    return 1.0f - 2.0f * rcpf(1.0f + ex2f(2.8853900817779268f * x));
}
__device__ __forceinline__ uint32_t packbf2(float a, float b) {
    __nv_bfloat16 ha = __float2bfloat16_rn(a), hb = __float2bfloat16_rn(b);
    return (uint32_t)__bfloat16_as_ushort(ha) |
           ((uint32_t)__bfloat16_as_ushort(hb) << 16);
}

// ---------------- mma ----------------
__device__ __forceinline__ void mma_bf16(float c[4],
    uint32_t a0, uint32_t a1, uint32_t a2, uint32_t a3,
    uint32_t b0, uint32_t b1) {
    asm volatile(
        "mma.sync.aligned.m16n8k16.row.col.f32.bf16.bf16.f32 "
        "{%0,%1,%2,%3},{%4,%5,%6,%7},{%8,%9},{%0,%1,%2,%3};"
        : "+f"(c[0]), "+f"(c[1]), "+f"(c[2]), "+f"(c[3])
        : "r"(a0), "r"(a1), "r"(a2), "r"(a3), "r"(b0), "r"(b1));
}

// ---------------- weight pack: fragment-ordered bf16 hi/lo image -----------
// frag = 256B: lane*8 + reg*4 + half*2. Element: k = (lane%4)*2+half+reg*8,
// n = lane/4. Per stage: [hi ksteps][lo ksteps] x NTN ntile fragments.
// gate row map r(j): j<32 -> j (i); else j+32 (g at 64.., o at 96..)
__global__ void _LSTM_pack(const float* __restrict__ w_ih0,
                           const float* __restrict__ w_ih_rest,
                           const float* __restrict__ b_ih,
                           const float* __restrict__ b_hh,
                           const float* __restrict__ fc_w,
                           const float* __restrict__ fc_b) {
    int i = blockIdx.x * blockDim.x + threadIdx.x;
    if (i < 40960) {
        int fid = i >> 7, r = i & 127;
        int lane = r >> 2, reg = (r >> 1) & 1, half = r & 1;
        int n = lane >> 2;
        int kel = (lane & 3) * 2 + half + reg * 8;
        int layer, kh, ntn, fl;
        if (fid < 96)       { layer = 0; kh = 4; ntn = 12; fl = fid; }
        else if (fid < 288) { layer = 1 + (fid - 96) / 48; kh = 2; ntn = 12;
                              fl = (fid - 96) % 48; }
        else                { layer = 5; kh = 2; ntn = 8; fl = fid - 288; }
        int kidx = fl / ntn, nt = fl % ntn;
        int is_lo = kidx >= kh;
        int k = (is_lo ? kidx - kh : kidx) * 16 + kel;
        int j = nt * 8 + n;
        float w;
        if (layer == 0)      { int rr = j < 32 ? j : j + 32; w = w_ih0[rr * 64 + k]; }
        else if (layer < 5)  { int rr = j < 32 ? j : j + 32;
                               w = w_ih_rest[(layer - 1) * 4096 + rr * 32 + k]; }
        else                 w = fc_w[j * 32 + k];
        __nv_bfloat16 hi = __float2bfloat16_rn(w);
        __nv_bfloat16 v = is_lo ?
            __float2bfloat16_rn(w - __bfloat162float(hi)) : hi;
        *(__nv_bfloat16*)(g_img + fid * 256 + lane * 8 + reg * 4 + half * 2) = v;
    } else if (i < 40960 + 544) {
        int b = i - 40960; float v;
        if (b < 480) {
            int l = b / 96, j = b % 96;
            int rr = j < 32 ? j : j + 32;
            v = b_ih[l * 128 + rr] + b_hh[l * 128 + rr];
        } else v = fc_b[b - 480];
        *(float*)(g_img + BIAS_OFF + b * 4) = v;
    }
}

// -------- one gate pass: 4 ntiles x 2 m-tiles, 3*KH ksteps, C zero-init ----
// A segments: seg0 hi+Whi, seg1 hi+Wlo, seg2 lo+Whi. hiKB = bytes of hi region.
template<int KH, int NTN>
__device__ __forceinline__ void gate_pass(
    const unsigned char* __restrict__ wimg, uint32_t wbase,
    const unsigned char* __restrict__ Abuf,
    int ntbase, int lane, int hiKB, float C[2][4][4])
{
#pragma unroll
    for (int m = 0; m < 2; m++)
#pragma unroll
        for (int nt = 0; nt < 4; nt++)
#pragma unroll
            for (int q = 0; q < 4; q++) C[m][nt][q] = 0.0f;

    const int g = lane >> 2, q4 = lane & 3;
#pragma unroll
    for (int t = 0; t < 3 * KH; t++) {
        const int seg = t / KH, tk = t % KH;
        const int aoff = (seg == 2 ? hiKB : 0) + 32 * tk;
        const int kg = (seg == 1) ? KH + tk : tk;
        uint32_t a[2][4];
#pragma unroll
        for (int m = 0; m < 2; m++) {
            const unsigned char* ab = Abuf + (m * 16 + g) * AP + aoff + 4 * q4;
            a[m][0] = *(const uint32_t*)(ab);
            a[m][1] = *(const uint32_t*)(ab + 8 * AP);
            a[m][2] = *(const uint32_t*)(ab + 16);
            a[m][3] = *(const uint32_t*)(ab + 8 * AP + 16);
        }
#pragma unroll
        for (int nt = 0; nt < 4; nt++) {
            const uint32_t* bf = (const uint32_t*)
                (wimg + wbase + (uint32_t)(kg * NTN + ntbase + nt) * 256 + lane * 8);
            uint32_t b0 = bf[0], b1 = bf[1];
            mma_bf16(C[0][nt], a[0][0], a[0][1], a[0][2], a[0][3], b0, b1);
            mma_bf16(C[1][nt], a[1][0], a[1][1], a[1][2], a[1][3], b0, b1);
        }
    }
}

// -------- one LSTM layer (2 m-tiles = 32 rows) --------
template<int KH>
__device__ __forceinline__ void lstm_layer_mma(
    const unsigned char* __restrict__ wimg, uint32_t wbase,
    const float* __restrict__ bias, unsigned char* Abuf, int lane, int hiKB)
{
    const int g = lane >> 2, q4 = lane & 3;
    float C[2][4][4], S[2][4][4];

    gate_pass<KH, 12>(wimg, wbase, Abuf, 0, lane, hiKB, C);   // i
#pragma unroll
    for (int nt = 0; nt < 4; nt++) {
        int col = nt * 8 + q4 * 2;
        float b0 = bias[col], b1 = bias[col + 1];
#pragma unroll
        for (int m = 0; m < 2; m++) {
            S[m][nt][0] = sigf(C[m][nt][0] + b0);
            S[m][nt][1] = sigf(C[m][nt][1] + b1);
            S[m][nt][2] = sigf(C[m][nt][2] + b0);
            S[m][nt][3] = sigf(C[m][nt][3] + b1);
        }
    }
    gate_pass<KH, 12>(wimg, wbase, Abuf, 4, lane, hiKB, C);   // g
#pragma unroll
    for (int nt = 0; nt < 4; nt++) {
        int col = 32 + nt * 8 + q4 * 2;
        float b0 = bias[col], b1 = bias[col + 1];
#pragma unroll
        for (int m = 0; m < 2; m++) {
            S[m][nt][0] *= tanhf_(C[m][nt][0] + b0);
            S[m][nt][1] *= tanhf_(C[m][nt][1] + b1);
            S[m][nt][2] *= tanhf_(C[m][nt][2] + b0);
            S[m][nt][3] *= tanhf_(C[m][nt][3] + b1);
        }
    }
    gate_pass<KH, 12>(wimg, wbase, Abuf, 8, lane, hiKB, C);   // o
#pragma unroll
    for (int nt = 0; nt < 4; nt++) {
        int col = 64 + nt * 8 + q4 * 2;
        float b0 = bias[col], b1 = bias[col + 1];
#pragma unroll
        for (int m = 0; m < 2; m++) {
            float h0 = sigf(C[m][nt][0] + b0) * tanhf_(S[m][nt][0]);
            float h1 = sigf(C[m][nt][1] + b1) * tanhf_(S[m][nt][1]);
            float h2 = sigf(C[m][nt][2] + b0) * tanhf_(S[m][nt][2]);
            float h3 = sigf(C[m][nt][3] + b1) * tanhf_(S[m][nt][3]);
            // rows m*16+g (h0,h1) and m*16+g+8 (h2,h3); cols j = nt*8+q4*2,+1
            unsigned char* r0 = Abuf + (m * 16 + g) * AP + 4 * (nt * 4 + q4);
            unsigned char* r1 = r0 + 8 * AP;
            *(uint32_t*)(r0)      = packbf2(h0, h1);
            *(uint32_t*)(r0 + 64) = packbf2(h0 - __bfloat162float(__float2bfloat16_rn(h0)),
                                            h1 - __bfloat162float(__float2bfloat16_rn(h1)));
            *(uint32_t*)(r1)      = packbf2(h2, h3);
            *(uint32_t*)(r1 + 64) = packbf2(h2 - __bfloat162float(__float2bfloat16_rn(h2)),
                                            h3 - __bfloat162float(__float2bfloat16_rn(h3)));
        }
    }
    __syncwarp();
}

// ---------------- main persistent kernel ----------------
__global__ void __launch_bounds__(NT, 1)
_LSTM_main(const float* __restrict__ x, float* __restrict__ out, int B) {
    extern __shared__ unsigned char smem[];
    const int tid = threadIdx.x;
    const int wid = tid >> 5;
    const int lane = tid & 31;
    const int g = lane >> 2, q4 = lane & 3;

    // copy fragment image + biases to smem once
#pragma unroll 4
    for (int p = tid; p < WIMG / 16; p += NT)
        ((uint4*)smem)[p] = ((const uint4*)g_img)[p];
    __syncthreads();

    unsigned char* Abuf = smem + WIMG + wid * WARP_ABUF;
    const float* bias = (const float*)(smem + BIAS_OFF);
    const float4* x4 = (const float4*)x;
    float4* o4 = (float4*)out;

    const int npair = (B + 511) >> 9;

#pragma unroll 1
    for (int it = blockIdx.x; it < npair; it += GRID) {
        const long long rowbase = (long long)it * 512 + wid * 32;

        // ---- load 32 x-rows, convert to bf16 hi/lo, warp-private stage ----
#pragma unroll
        for (int i = 0; i < 16; i++) {
            int p = lane + i * 32;
            int r = p >> 4, c4 = p & 15;
            long long grow = rowbase + r;
            float4 v = (grow < B) ? x4[grow * 16 + c4]
                                  : make_float4(0.f, 0.f, 0.f, 0.f);
            uint32_t hi0 = packbf2(v.x, v.y), hi1 = packbf2(v.z, v.w);
            float lx = v.x - __bfloat162float(__float2bfloat16_rn(v.x));
            float ly = v.y - __bfloat162float(__float2bfloat16_rn(v.y));
            float lz = v.z - __bfloat162float(__float2bfloat16_rn(v.z));
            float lw = v.w - __bfloat162float(__float2bfloat16_rn(v.w));
            uint32_t lo0 = packbf2(lx, ly), lo1 = packbf2(lz, lw);
            unsigned char* dst = Abuf + r * AP + 8 * c4;
            *(uint2*)dst         = make_uint2(hi0, hi1);
            *(uint2*)(dst + 128) = make_uint2(lo0, lo1);
        }
        __syncwarp();

        // ---- 5 LSTM layers ----
        lstm_layer_mma<4>(smem, WB_L0, bias,        Abuf, lane, 128);
        lstm_layer_mma<2>(smem, WB_L1, bias + 96,   Abuf, lane, 64);
        lstm_layer_mma<2>(smem, WB_L2, bias + 192,  Abuf, lane, 64);
        lstm_layer_mma<2>(smem, WB_L3, bias + 288,  Abuf, lane, 64);
        lstm_layer_mma<2>(smem, WB_L4, bias + 384,  Abuf, lane, 64);

        // ---- fc: both n-halves before staging (stage clobbers h region) ----
        float C1[2][4][4], C2[2][4][4];
        gate_pass<2, 8>(smem, WB_FC, Abuf, 0, lane, 64, C1);
        gate_pass<2, 8>(smem, WB_FC, Abuf, 4, lane, 64, C2);
        const float* fb = bias + 480;
#pragma unroll
        for (int half = 0; half < 2; half++) {
            float (*C)[4][4] = half ? C2 : C1;
#pragma unroll
            for (int nt = 0; nt < 4; nt++) {
                int col = half * 32 + nt * 8 + q4 * 2;
                float b0 = fb[col], b1 = fb[col + 1];
#pragma unroll
                for (int m = 0; m < 2; m++) {
                    unsigned char* r0 = Abuf + (m * 16 + g) * AP + 4 * col;
                    unsigned char* r1 = r0 + 8 * AP;
                    ((float*)r0)[0] = C[m][nt][0] + b0;
                    ((float*)r0)[1] = C[m][nt][1] + b1;
                    ((float*)r1)[0] = C[m][nt][2] + b0;
                    ((float*)r1)[1] = C[m][nt][3] + b1;
                }
            }
        }
        __syncwarp();

        // ---- coalesced f32 store ----
#pragma unroll
        for (int i = 0; i < 16; i++) {
            int p = lane + i * 32;
            int r = p >> 4, c4 = p & 15;
            long long grow = rowbase + r;
            if (grow < B)
                o4[grow * 16 + c4] = *(const float4*)(Abuf + r * AP + 16 * c4);
        }
        __syncwarp();
    }
}

// ---------------- launch ----------------
extern "C" void kernel_launch(void* const* d_in, const int* in_sizes, int n_in,
                              void* d_out, int out_size) {
    (void)n_in; (void)out_size;
    const float* x         = (const float*)d_in[0];
    const float* w_ih0     = (const float*)d_in[1];
    // d_in[2] = w_hh0      (unused: h0 == 0, T == 1)
    const float* w_ih_rest = (const float*)d_in[3];
    // d_in[4] = w_hh_rest  (unused)
    const float* b_ih      = (const float*)d_in[5];
    const float* b_hh      = (const float*)d_in[6];
    const float* fc_w      = (const float*)d_in[7];
    const float* fc_b      = (const float*)d_in[8];
    float* out = (float*)d_out;

    int B = in_sizes[0] / 64;

    _LSTM_pack<<<(40960 + 544 + 255) / 256, 256>>>(
        w_ih0, w_ih_rest, b_ih, b_hh, fc_w, fc_b);

    cudaFuncSetAttribute(_LSTM_main,
                         cudaFuncAttributeMaxDynamicSharedMemorySize, SMEM_BYTES);
    int npair = (B + 511) / 512;
    int grid = npair < GRID ? npair : GRID;
    _LSTM_main<<<grid, NT, SMEM_BYTES>>>(x, out, B);
}

// round 5
// speedup vs baseline: 2.7274x; 1.5267x over previous
#include <cuda_runtime.h>
#include <cuda_bf16.h>
#include <cstdint>

// ============================================================================
// T=1, h0=c0=0 => w_hh* unused, f-gate unused. Chain of small GEMMs on HMMA
// (mma.sync m16n8k16 bf16; tcgen05 blocked by compute_103 virtual arch).
// bf16x3 accuracy: A segments [hi, hi, lo] vs W segments [Whi, Wlo, Whi].
// R5: A fragments live in REGISTERS for the whole layer (loaded once);
// i/g/o computed together per 8-column n-group (no S buffer, 6 independent
// MMA chains per group) -> kills the LDS->MMA latency chains of R4.
// Persistent: 148 CTAs x 512 threads; warp owns 32 rows, warp-private A smem.
// ============================================================================

#define NT    512
#define GRID  148
#define AP    272                        // A-buffer row pitch (bytes)
#define WIMG  84096                      // 81920B frags + 544*4B biases
#define WARP_ABUF (32 * AP)
#define SMEM_BYTES (WIMG + 16 * WARP_ABUF)

#define WB_L0 0
#define WB_L1 24576
#define WB_L2 36864
#define WB_L3 49152
#define WB_L4 61440
#define WB_FC 73728
#define BIAS_OFF 81920

__device__ __align__(16) unsigned char g_img[WIMG];

// ---------------- fast activations ----------------
__device__ __forceinline__ float ex2f(float x) {
    float y; asm("ex2.approx.f32 %0, %1;" : "=f"(y) : "f"(x)); return y;
}
__device__ __forceinline__ float rcpf(float x) {
    float y; asm("rcp.approx.f32 %0, %1;" : "=f"(y) : "f"(x)); return y;
}
__device__ __forceinline__ float sigf(float x) {
    return rcpf(1.0f + ex2f(-1.4426950408889634f * x));
}
__device__ __forceinline__ float tanhf_(float x) {
    return 1.0f - 2.0f * rcpf(1.0f + ex2f(2.8853900817779268f * x));
}
__device__ __forceinline__ uint32_t packbf2(float a, float b) {
    __nv_bfloat16 ha = __float2bfloat16_rn(a), hb = __float2bfloat16_rn(b);
    return (uint32_t)__bfloat16_as_ushort(ha) |
           ((uint32_t)__bfloat16_as_ushort(hb) << 16);
}
__device__ __forceinline__ float bflo(float v) {
    return v - __bfloat162float(__float2bfloat16_rn(v));
}

// ---------------- mma ----------------
__device__ __forceinline__ void mma_bf16(float c[4],
    const uint32_t a[4], uint32_t b0, uint32_t b1) {
    asm volatile(
        "mma.sync.aligned.m16n8k16.row.col.f32.bf16.bf16.f32 "
        "{%0,%1,%2,%3},{%4,%5,%6,%7},{%8,%9},{%0,%1,%2,%3};"
        : "+f"(c[0]), "+f"(c[1]), "+f"(c[2]), "+f"(c[3])
        : "r"(a[0]), "r"(a[1]), "r"(a[2]), "r"(a[3]), "r"(b0), "r"(b1));
}

// ---------------- weight pack (identical to R4; layout validated) ----------
__global__ void _LSTM_pack(const float* __restrict__ w_ih0,
                           const float* __restrict__ w_ih_rest,
                           const float* __restrict__ b_ih,
                           const float* __restrict__ b_hh,
                           const float* __restrict__ fc_w,
                           const float* __restrict__ fc_b) {
    int i = blockIdx.x * blockDim.x + threadIdx.x;
    if (i < 40960) {
        int fid = i >> 7, r = i & 127;
        int lane = r >> 2, reg = (r >> 1) & 1, half = r & 1;
        int n = lane >> 2;
        int kel = (lane & 3) * 2 + half + reg * 8;
        int layer, kh, ntn, fl;
        if (fid < 96)       { layer = 0; kh = 4; ntn = 12; fl = fid; }
        else if (fid < 288) { layer = 1 + (fid - 96) / 48; kh = 2; ntn = 12;
                              fl = (fid - 96) % 48; }
        else                { layer = 5; kh = 2; ntn = 8; fl = fid - 288; }
        int kidx = fl / ntn, nt = fl % ntn;
        int is_lo = kidx >= kh;
        int k = (is_lo ? kidx - kh : kidx) * 16 + kel;
        int j = nt * 8 + n;
        float w;
        if (layer == 0)      { int rr = j < 32 ? j : j + 32; w = w_ih0[rr * 64 + k]; }
        else if (layer < 5)  { int rr = j < 32 ? j : j + 32;
                               w = w_ih_rest[(layer - 1) * 4096 + rr * 32 + k]; }
        else                 w = fc_w[j * 32 + k];
        __nv_bfloat16 hi = __float2bfloat16_rn(w);
        __nv_bfloat16 v = is_lo ?
            __float2bfloat16_rn(w - __bfloat162float(hi)) : hi;
        *(__nv_bfloat16*)(g_img + fid * 256 + lane * 8 + reg * 4 + half * 2) = v;
    } else if (i < 40960 + 544) {
        int b = i - 40960; float v;
        if (b < 480) {
            int l = b / 96, j = b % 96;
            int rr = j < 32 ? j : j + 32;
            v = b_ih[l * 128 + rr] + b_hh[l * 128 + rr];
        } else v = fc_b[b - 480];
        *(float*)(g_img + BIAS_OFF + b * 4) = v;
    }
}

// -------- load A fragments (hi+lo) for the layer into registers --------
template<int KH>
__device__ __forceinline__ void load_A(
    const unsigned char* __restrict__ Abuf, int lane, int hiKB,
    uint32_t Ah[2][KH][4], uint32_t Al[2][KH][4])
{
    const int g = lane >> 2, q4 = lane & 3;
#pragma unroll
    for (int m = 0; m < 2; m++)
#pragma unroll
        for (int tk = 0; tk < KH; tk++) {
            const unsigned char* ab = Abuf + (m * 16 + g) * AP + 32 * tk + 4 * q4;
            Ah[m][tk][0] = *(const uint32_t*)ab;
            Ah[m][tk][1] = *(const uint32_t*)(ab + 8 * AP);
            Ah[m][tk][2] = *(const uint32_t*)(ab + 16);
            Ah[m][tk][3] = *(const uint32_t*)(ab + 8 * AP + 16);
            const unsigned char* al = ab + hiKB;
            Al[m][tk][0] = *(const uint32_t*)al;
            Al[m][tk][1] = *(const uint32_t*)(al + 8 * AP);
            Al[m][tk][2] = *(const uint32_t*)(al + 16);
            Al[m][tk][3] = *(const uint32_t*)(al + 8 * AP + 16);
        }
    __syncwarp();   // all lanes' A in regs before any h writes below
}

// -------- one LSTM layer: A in regs, i/g/o fused per 8-column n-group ------
template<int KH>
__device__ __forceinline__ void lstm_layer_reg(
    const unsigned char* __restrict__ wimg, uint32_t wbase,
    const float* __restrict__ bias, unsigned char* __restrict__ Abuf,
    int lane, int hiKB)
{
    const int g = lane >> 2, q4 = lane & 3;
    uint32_t Ah[2][KH][4], Al[2][KH][4];
    load_A<KH>(Abuf, lane, hiKB, Ah, Al);

    const unsigned char* wp = wimg + wbase + lane * 8;

#pragma unroll
    for (int ntj = 0; ntj < 4; ntj++) {
        float Ci[2][4], Cg[2][4], Co[2][4];
#pragma unroll
        for (int m = 0; m < 2; m++)
#pragma unroll
            for (int q = 0; q < 4; q++) {
                Ci[m][q] = 0.f; Cg[m][q] = 0.f; Co[m][q] = 0.f;
            }
#pragma unroll
        for (int t = 0; t < 3 * KH; t++) {
            const int seg = t / KH, tk = t % KH;
            const int kg = (seg == 1) ? KH + tk : tk;
            const uint32_t* bi = (const uint32_t*)(wp + (uint32_t)(kg * 12 + ntj) * 256);
            const uint32_t* bg = (const uint32_t*)(wp + (uint32_t)(kg * 12 + 4 + ntj) * 256);
            const uint32_t* bo = (const uint32_t*)(wp + (uint32_t)(kg * 12 + 8 + ntj) * 256);
            uint32_t i0 = bi[0], i1 = bi[1];
            uint32_t g0 = bg[0], g1 = bg[1];
            uint32_t o0 = bo[0], o1 = bo[1];
#pragma unroll
            for (int m = 0; m < 2; m++) {
                const uint32_t* A = (seg == 2) ? Al[m][tk] : Ah[m][tk];
                mma_bf16(Ci[m], A, i0, i1);
                mma_bf16(Cg[m], A, g0, g1);
                mma_bf16(Co[m], A, o0, o1);
            }
        }
        const int col = ntj * 8 + q4 * 2;
        const float bI0 = bias[col],      bI1 = bias[col + 1];
        const float bG0 = bias[32 + col], bG1 = bias[33 + col];
        const float bO0 = bias[64 + col], bO1 = bias[65 + col];
#pragma unroll
        for (int m = 0; m < 2; m++) {
            float h0 = sigf(Co[m][0] + bO0) *
                       tanhf_(sigf(Ci[m][0] + bI0) * tanhf_(Cg[m][0] + bG0));
            float h1 = sigf(Co[m][1] + bO1) *
                       tanhf_(sigf(Ci[m][1] + bI1) * tanhf_(Cg[m][1] + bG1));
            float h2 = sigf(Co[m][2] + bO0) *
                       tanhf_(sigf(Ci[m][2] + bI0) * tanhf_(Cg[m][2] + bG0));
            float h3 = sigf(Co[m][3] + bO1) *
                       tanhf_(sigf(Ci[m][3] + bI1) * tanhf_(Cg[m][3] + bG1));
            unsigned char* r0 = Abuf + (m * 16 + g) * AP + 4 * (ntj * 4 + q4);
            unsigned char* r1 = r0 + 8 * AP;
            *(uint32_t*)r0        = packbf2(h0, h1);
            *(uint32_t*)(r0 + 64) = packbf2(bflo(h0), bflo(h1));
            *(uint32_t*)r1        = packbf2(h2, h3);
            *(uint32_t*)(r1 + 64) = packbf2(bflo(h2), bflo(h3));
        }
    }
    __syncwarp();
}

// -------- fc: 8 n-groups, A in regs, f32 outputs staged to Abuf --------
__device__ __forceinline__ void fc_reg(
    const unsigned char* __restrict__ wimg,
    const float* __restrict__ fb, unsigned char* __restrict__ Abuf, int lane)
{
    const int g = lane >> 2, q4 = lane & 3;
    uint32_t Ah[2][2][4], Al[2][2][4];
    load_A<2>(Abuf, lane, 64, Ah, Al);

    const unsigned char* wp = wimg + WB_FC + lane * 8;

#pragma unroll
    for (int ntj = 0; ntj < 8; ntj++) {
        float C[2][4];
#pragma unroll
        for (int m = 0; m < 2; m++)
#pragma unroll
            for (int q = 0; q < 4; q++) C[m][q] = 0.f;
#pragma unroll
        for (int t = 0; t < 6; t++) {
            const int seg = t / 2, tk = t % 2;
            const int kg = (seg == 1) ? 2 + tk : tk;
            const uint32_t* bf = (const uint32_t*)(wp + (uint32_t)(kg * 8 + ntj) * 256);
            uint32_t b0 = bf[0], b1 = bf[1];
#pragma unroll
            for (int m = 0; m < 2; m++) {
                const uint32_t* A = (seg == 2) ? Al[m][tk] : Ah[m][tk];
                mma_bf16(C[m], A, b0, b1);
            }
        }
        const int col = ntj * 8 + q4 * 2;
        const float b0 = fb[col], b1 = fb[col + 1];
#pragma unroll
        for (int m = 0; m < 2; m++) {
            float* r0 = (float*)(Abuf + (m * 16 + g) * AP + 4 * col);
            float* r1 = (float*)((unsigned char*)r0 + 8 * AP);
            r0[0] = C[m][0] + b0; r0[1] = C[m][1] + b1;
            r1[0] = C[m][2] + b0; r1[1] = C[m][3] + b1;
        }
    }
    __syncwarp();
}

// ---------------- main persistent kernel ----------------
__global__ void __launch_bounds__(NT, 1)
_LSTM_main(const float* __restrict__ x, float* __restrict__ out, int B) {
    extern __shared__ unsigned char smem[];
    const int tid = threadIdx.x;
    const int wid = tid >> 5;
    const int lane = tid & 31;

    // copy fragment image + biases to smem once
#pragma unroll 4
    for (int p = tid; p < WIMG / 16; p += NT)
        ((uint4*)smem)[p] = ((const uint4*)g_img)[p];
    __syncthreads();

    unsigned char* Abuf = smem + WIMG + wid * WARP_ABUF;
    const float* bias = (const float*)(smem + BIAS_OFF);
    const float4* x4 = (const float4*)x;
    float4* o4 = (float4*)out;

    const int npair = (B + 511) >> 9;

#pragma unroll 1
    for (int it = blockIdx.x; it < npair; it += GRID) {
        const long long rowbase = (long long)it * 512 + wid * 32;

        // ---- load 32 x-rows, convert to bf16 hi/lo, warp-private stage ----
#pragma unroll
        for (int i = 0; i < 16; i++) {
            int p = lane + i * 32;
            int r = p >> 4, c4 = p & 15;
            long long grow = rowbase + r;
            float4 v = (grow < B) ? x4[grow * 16 + c4]
                                  : make_float4(0.f, 0.f, 0.f, 0.f);
            uint32_t hi0 = packbf2(v.x, v.y), hi1 = packbf2(v.z, v.w);
            uint32_t lo0 = packbf2(bflo(v.x), bflo(v.y));
            uint32_t lo1 = packbf2(bflo(v.z), bflo(v.w));
            unsigned char* dst = Abuf + r * AP + 8 * c4;
            *(uint2*)dst         = make_uint2(hi0, hi1);
            *(uint2*)(dst + 128) = make_uint2(lo0, lo1);
        }
        __syncwarp();

        // ---- 5 LSTM layers + fc ----
        lstm_layer_reg<4>(smem, WB_L0, bias,       Abuf, lane, 128);
        lstm_layer_reg<2>(smem, WB_L1, bias + 96,  Abuf, lane, 64);
        lstm_layer_reg<2>(smem, WB_L2, bias + 192, Abuf, lane, 64);
        lstm_layer_reg<2>(smem, WB_L3, bias + 288, Abuf, lane, 64);
        lstm_layer_reg<2>(smem, WB_L4, bias + 384, Abuf, lane, 64);
        fc_reg(smem, bias + 480, Abuf, lane);

        // ---- coalesced f32 store ----
#pragma unroll
        for (int i = 0; i < 16; i++) {
            int p = lane + i * 32;
            int r = p >> 4, c4 = p & 15;
            long long grow = rowbase + r;
            if (grow < B)
                o4[grow * 16 + c4] = *(const float4*)(Abuf + r * AP + 16 * c4);
        }
        __syncwarp();
    }
}

// ---------------- launch ----------------
extern "C" void kernel_launch(void* const* d_in, const int* in_sizes, int n_in,
                              void* d_out, int out_size) {
    (void)n_in; (void)out_size;
    const float* x         = (const float*)d_in[0];
    const float* w_ih0     = (const float*)d_in[1];
    // d_in[2] = w_hh0      (unused: h0 == 0, T == 1)
    const float* w_ih_rest = (const float*)d_in[3];
    // d_in[4] = w_hh_rest  (unused)
    const float* b_ih      = (const float*)d_in[5];
    const float* b_hh      = (const float*)d_in[6];
    const float* fc_w      = (const float*)d_in[7];
    const float* fc_b      = (const float*)d_in[8];
    float* out = (float*)d_out;

    int B = in_sizes[0] / 64;

    _LSTM_pack<<<(40960 + 544 + 255) / 256, 256>>>(
        w_ih0, w_ih_rest, b_ih, b_hh, fc_w, fc_b);

    cudaFuncSetAttribute(_LSTM_main,
                         cudaFuncAttributeMaxDynamicSharedMemorySize, SMEM_BYTES);
    int npair = (B + 511) / 512;
    int grid = npair < GRID ? npair : GRID;
    _LSTM_main<<<grid, NT, SMEM_BYTES>>>(x, out, B);
}

// round 6
// speedup vs baseline: 2.8410x; 1.0416x over previous
#include <cuda_runtime.h>
#include <cuda_bf16.h>
#include <cstdint>

// ============================================================================
// T=1, h0=c0=0 => w_hh* unused, f-gate unused. Chain of small GEMMs on HMMA
// (mma.sync m16n8k16 bf16; tcgen05 blocked by compute_103 virtual arch).
// bf16x3: A segs [hi,hi,lo] vs W segs [Whi,Wlo,Whi].
// R6: (a) fused activation: sig(i)tanh(g) and sig(o)tanh(c) each via ONE rcp
//     (6 MUFU/h instead of 8), biases pre-scaled by log2e in pack kernel;
// (b) ntj-lag software pipeline: MMA(ntj) co-scheduled with EPI(ntj-1),
//     double-buffered accumulators; A_hi in regs, A_lo via LDS in seg2;
//     smem h regions ping-pong [0,128)<->[128,256) so lagged EPI writes
//     never alias the A_lo reads.
// Persistent: 148 CTAs x 512 threads; warp owns 32 rows, warp-private A smem.
// ============================================================================

#define NT    512
#define GRID  148
#define AP    272
#define WIMG  84096
#define WARP_ABUF (32 * AP)
#define SMEM_BYTES (WIMG + 16 * WARP_ABUF)

#define WB_L0 0
#define WB_L1 24576
#define WB_L2 36864
#define WB_L3 49152
#define WB_L4 61440
#define WB_FC 73728
#define BIAS_OFF 81920

#define LOG2E  1.4426950408889634f
#define LOG2E2 2.8853901617765427f

__device__ __align__(16) unsigned char g_img[WIMG];

// ---------------- fast math ----------------
__device__ __forceinline__ float ex2f(float x) {
    float y; asm("ex2.approx.f32 %0, %1;" : "=f"(y) : "f"(x)); return y;
}
__device__ __forceinline__ float rcpf(float x) {
    float y; asm("rcp.approx.f32 %0, %1;" : "=f"(y) : "f"(x)); return y;
}
__device__ __forceinline__ uint32_t packbf2(float a, float b) {
    __nv_bfloat16 ha = __float2bfloat16_rn(a), hb = __float2bfloat16_rn(b);
    return (uint32_t)__bfloat16_as_ushort(ha) |
           ((uint32_t)__bfloat16_as_ushort(hb) << 16);
}
__device__ __forceinline__ float bflo(float v) {
    return v - __bfloat162float(__float2bfloat16_rn(v));
}

// fused LSTM activation: h = sig(o)*tanh(sig(i)*tanh(g)).
// biases arrive pre-scaled: bik = bI*log2e, bgk = bG*2*log2e, bok = bO*log2e.
__device__ __forceinline__ float act_h(float ci, float cg, float co,
                                       float bik, float bgk, float bok) {
    float A  = ex2f(fmaf(ci, LOG2E,  bik));    // e^i
    float Bv = ex2f(fmaf(cg, LOG2E2, bgk));    // e^{2g}
    float r1 = rcpf((A + 1.f) * (Bv + 1.f));
    float c2k = (A * (Bv - 1.f)) * LOG2E2 * r1;  // 2*log2e * sig(i)tanh(g)
    float Cc = ex2f(fmaf(co, LOG2E,  bok));    // e^o
    float D  = ex2f(c2k);                      // e^{2c}
    return (Cc * (D - 1.f)) * rcpf((Cc + 1.f) * (D + 1.f));
}

// ---------------- mma ----------------
__device__ __forceinline__ void mma_bf16(float c[4],
    const uint32_t a[4], uint32_t b0, uint32_t b1) {
    asm volatile(
        "mma.sync.aligned.m16n8k16.row.col.f32.bf16.bf16.f32 "
        "{%0,%1,%2,%3},{%4,%5,%6,%7},{%8,%9},{%0,%1,%2,%3};"
        : "+f"(c[0]), "+f"(c[1]), "+f"(c[2]), "+f"(c[3])
        : "r"(a[0]), "r"(a[1]), "r"(a[2]), "r"(a[3]), "r"(b0), "r"(b1));
}

// ---------------- weight pack (R4 layout; biases now pre-scaled) ----------
__global__ void _LSTM_pack(const float* __restrict__ w_ih0,
                           const float* __restrict__ w_ih_rest,
                           const float* __restrict__ b_ih,
                           const float* __restrict__ b_hh,
                           const float* __restrict__ fc_w,
                           const float* __restrict__ fc_b) {
    int i = blockIdx.x * blockDim.x + threadIdx.x;
    if (i < 40960) {
        int fid = i >> 7, r = i & 127;
        int lane = r >> 2, reg = (r >> 1) & 1, half = r & 1;
        int n = lane >> 2;
        int kel = (lane & 3) * 2 + half + reg * 8;
        int layer, kh, ntn, fl;
        if (fid < 96)       { layer = 0; kh = 4; ntn = 12; fl = fid; }
        else if (fid < 288) { layer = 1 + (fid - 96) / 48; kh = 2; ntn = 12;
                              fl = (fid - 96) % 48; }
        else                { layer = 5; kh = 2; ntn = 8; fl = fid - 288; }
        int kidx = fl / ntn, nt = fl % ntn;
        int is_lo = kidx >= kh;
        int k = (is_lo ? kidx - kh : kidx) * 16 + kel;
        int j = nt * 8 + n;
        float w;
        if (layer == 0)      { int rr = j < 32 ? j : j + 32; w = w_ih0[rr * 64 + k]; }
        else if (layer < 5)  { int rr = j < 32 ? j : j + 32;
                               w = w_ih_rest[(layer - 1) * 4096 + rr * 32 + k]; }
        else                 w = fc_w[j * 32 + k];
        __nv_bfloat16 hi = __float2bfloat16_rn(w);
        __nv_bfloat16 v = is_lo ?
            __float2bfloat16_rn(w - __bfloat162float(hi)) : hi;
        *(__nv_bfloat16*)(g_img + fid * 256 + lane * 8 + reg * 4 + half * 2) = v;
    } else if (i < 40960 + 544) {
        int b = i - 40960; float v;
        if (b < 480) {
            int l = b / 96, j = b % 96;
            int rr = j < 32 ? j : j + 32;
            v = b_ih[l * 128 + rr] + b_hh[l * 128 + rr];
            v *= (j >= 32 && j < 64) ? LOG2E2 : LOG2E;   // g rows: 2*log2e
        } else v = fc_b[b - 480];
        *(float*)(g_img + BIAS_OFF + b * 4) = v;
    }
}

// -------- one 96-col LSTM layer with ntj-lag pipeline --------
// A_hi in regs (from in_hi); A_lo LDS'd in seg2 (from in_lo);
// h written to out_off (disjoint from in_lo region).
template<int KH>
__device__ __forceinline__ void layer96(
    const unsigned char* __restrict__ wimg, uint32_t wbase,
    const float* __restrict__ biasK, unsigned char* __restrict__ Abuf,
    int in_hi, int in_lo, int out_off, int lane)
{
    const int g = lane >> 2, q4 = lane & 3;
    uint32_t Ah[2][KH][4];
#pragma unroll
    for (int m = 0; m < 2; m++)
#pragma unroll
        for (int tk = 0; tk < KH; tk++) {
            const unsigned char* ab =
                Abuf + in_hi + (m * 16 + g) * AP + 32 * tk + 4 * q4;
            Ah[m][tk][0] = *(const uint32_t*)ab;
            Ah[m][tk][1] = *(const uint32_t*)(ab + 8 * AP);
            Ah[m][tk][2] = *(const uint32_t*)(ab + 16);
            Ah[m][tk][3] = *(const uint32_t*)(ab + 8 * AP + 16);
        }
    __syncwarp();

    const unsigned char* wp = wimg + wbase + lane * 8;
    const unsigned char* lo0 = Abuf + in_lo + g * AP + 4 * q4;
    const unsigned char* lo1 = lo0 + 16 * AP;

    float C[2][6][4];   // double-buffered: [buf][gate*2+m][quad]

#pragma unroll
    for (int p = 0; p < 5; p++) {
        if (p < 4) {
            float (*Cc)[4] = C[p & 1];
#pragma unroll
            for (int ch = 0; ch < 6; ch++)
#pragma unroll
                for (int q = 0; q < 4; q++) Cc[ch][q] = 0.f;
#pragma unroll
            for (int t = 0; t < 3 * KH; t++) {
                const int seg = t / KH, tk = t % KH;
                const int kg = (seg == 1) ? KH + tk : tk;
                uint32_t Ax[2][4];
#pragma unroll
                for (int m = 0; m < 2; m++) {
                    if (seg == 2) {
                        const unsigned char* ab = (m ? lo1 : lo0) + 32 * tk;
                        Ax[m][0] = *(const uint32_t*)ab;
                        Ax[m][1] = *(const uint32_t*)(ab + 8 * AP);
                        Ax[m][2] = *(const uint32_t*)(ab + 16);
                        Ax[m][3] = *(const uint32_t*)(ab + 8 * AP + 16);
                    } else {
                        Ax[m][0] = Ah[m][tk][0]; Ax[m][1] = Ah[m][tk][1];
                        Ax[m][2] = Ah[m][tk][2]; Ax[m][3] = Ah[m][tk][3];
                    }
                }
#pragma unroll
                for (int gate = 0; gate < 3; gate++) {
                    const uint32_t* bf = (const uint32_t*)
                        (wp + (uint32_t)(kg * 12 + gate * 4 + p) * 256);
                    uint32_t b0 = bf[0], b1 = bf[1];
                    mma_bf16(Cc[gate * 2 + 0], Ax[0], b0, b1);
                    mma_bf16(Cc[gate * 2 + 1], Ax[1], b0, b1);
                }
            }
        }
        if (p > 0) {
            const int ntj = p - 1;
            float (*Cp)[4] = C[(p - 1) & 1];
            const int col = ntj * 8 + q4 * 2;
            const float bi0 = biasK[col],      bi1 = biasK[col + 1];
            const float bg0 = biasK[32 + col], bg1 = biasK[33 + col];
            const float bo0 = biasK[64 + col], bo1 = biasK[65 + col];
#pragma unroll
            for (int m = 0; m < 2; m++) {
                float h0 = act_h(Cp[m][0], Cp[2 + m][0], Cp[4 + m][0], bi0, bg0, bo0);
                float h1 = act_h(Cp[m][1], Cp[2 + m][1], Cp[4 + m][1], bi1, bg1, bo1);
                float h2 = act_h(Cp[m][2], Cp[2 + m][2], Cp[4 + m][2], bi0, bg0, bo0);
                float h3 = act_h(Cp[m][3], Cp[2 + m][3], Cp[4 + m][3], bi1, bg1, bo1);
                unsigned char* r0 =
                    Abuf + out_off + (m * 16 + g) * AP + 4 * (ntj * 4 + q4);
                unsigned char* r1 = r0 + 8 * AP;
                *(uint32_t*)r0        = packbf2(h0, h1);
                *(uint32_t*)(r0 + 64) = packbf2(bflo(h0), bflo(h1));
                *(uint32_t*)r1        = packbf2(h2, h3);
                *(uint32_t*)(r1 + 64) = packbf2(bflo(h2), bflo(h3));
            }
        }
    }
    __syncwarp();
}

// -------- fc: A hi+lo fully in regs (output clobbers input region) --------
__device__ __forceinline__ void fc_stage(
    const unsigned char* __restrict__ wimg,
    const float* __restrict__ fb, unsigned char* __restrict__ Abuf, int lane)
{
    const int g = lane >> 2, q4 = lane & 3;
    uint32_t Ah[2][2][4], Al[2][2][4];
#pragma unroll
    for (int m = 0; m < 2; m++)
#pragma unroll
        for (int tk = 0; tk < 2; tk++) {
            const unsigned char* ab =
                Abuf + (m * 16 + g) * AP + 32 * tk + 4 * q4;
            Ah[m][tk][0] = *(const uint32_t*)ab;
            Ah[m][tk][1] = *(const uint32_t*)(ab + 8 * AP);
            Ah[m][tk][2] = *(const uint32_t*)(ab + 16);
            Ah[m][tk][3] = *(const uint32_t*)(ab + 8 * AP + 16);
            const unsigned char* al = ab + 64;
            Al[m][tk][0] = *(const uint32_t*)al;
            Al[m][tk][1] = *(const uint32_t*)(al + 8 * AP);
            Al[m][tk][2] = *(const uint32_t*)(al + 16);
            Al[m][tk][3] = *(const uint32_t*)(al + 8 * AP + 16);
        }
    __syncwarp();

    const unsigned char* wp = wimg + WB_FC + lane * 8;

#pragma unroll
    for (int ntj = 0; ntj < 8; ntj++) {
        float C2[2][4];
#pragma unroll
        for (int m = 0; m < 2; m++)
#pragma unroll
            for (int q = 0; q < 4; q++) C2[m][q] = 0.f;
#pragma unroll
        for (int t = 0; t < 6; t++) {
            const int seg = t / 2, tk = t % 2;
            const int kg = (seg == 1) ? 2 + tk : tk;
            const uint32_t* bf = (const uint32_t*)
                (wp + (uint32_t)(kg * 8 + ntj) * 256);
            uint32_t b0 = bf[0], b1 = bf[1];
#pragma unroll
            for (int m = 0; m < 2; m++) {
                const uint32_t* A = (seg == 2) ? Al[m][tk] : Ah[m][tk];
                mma_bf16(C2[m], A, b0, b1);
            }
        }
        const int col = ntj * 8 + q4 * 2;
        const float b0 = fb[col], b1 = fb[col + 1];
#pragma unroll
        for (int m = 0; m < 2; m++) {
            float* r0 = (float*)(Abuf + (m * 16 + g) * AP + 4 * col);
            float* r1 = (float*)((unsigned char*)r0 + 8 * AP);
            r0[0] = C2[m][0] + b0; r0[1] = C2[m][1] + b1;
            r1[0] = C2[m][2] + b0; r1[1] = C2[m][3] + b1;
        }
    }
    __syncwarp();
}

// ---------------- main persistent kernel ----------------
__global__ void __launch_bounds__(NT, 1)
_LSTM_main(const float* __restrict__ x, float* __restrict__ out, int B) {
    extern __shared__ unsigned char smem[];
    const int tid = threadIdx.x;
    const int wid = tid >> 5;
    const int lane = tid & 31;

#pragma unroll 4
    for (int p = tid; p < WIMG / 16; p += NT)
        ((uint4*)smem)[p] = ((const uint4*)g_img)[p];
    __syncthreads();

    unsigned char* Abuf = smem + WIMG + wid * WARP_ABUF;
    const float* biasK = (const float*)(smem + BIAS_OFF);
    const float4* x4 = (const float4*)x;
    float4* o4 = (float4*)out;

    const int npair = (B + 511) >> 9;

#pragma unroll 1
    for (int it = blockIdx.x; it < npair; it += GRID) {
        const long long rowbase = (long long)it * 512 + wid * 32;

        // ---- load 32 x-rows, bf16 hi [0,128) / lo [128,256) ----
#pragma unroll
        for (int i = 0; i < 16; i++) {
            int p = lane + i * 32;
            int r = p >> 4, c4 = p & 15;
            long long grow = rowbase + r;
            float4 v = (grow < B) ? x4[grow * 16 + c4]
                                  : make_float4(0.f, 0.f, 0.f, 0.f);
            uint32_t hi0 = packbf2(v.x, v.y), hi1 = packbf2(v.z, v.w);
            uint32_t lo0 = packbf2(bflo(v.x), bflo(v.y));
            uint32_t lo1 = packbf2(bflo(v.z), bflo(v.w));
            unsigned char* dst = Abuf + r * AP + 8 * c4;
            *(uint2*)dst         = make_uint2(hi0, hi1);
            *(uint2*)(dst + 128) = make_uint2(lo0, lo1);
        }
        __syncwarp();

        // ---- 5 LSTM layers (h regions ping-pong) + fc ----
        layer96<4>(smem, WB_L0, biasK,       Abuf,   0, 128,   0, lane);
        layer96<2>(smem, WB_L1, biasK + 96,  Abuf,   0,  64, 128, lane);
        layer96<2>(smem, WB_L2, biasK + 192, Abuf, 128, 192,   0, lane);
        layer96<2>(smem, WB_L3, biasK + 288, Abuf,   0,  64, 128, lane);
        layer96<2>(smem, WB_L4, biasK + 384, Abuf, 128, 192,   0, lane);
        fc_stage(smem, biasK + 480, Abuf, lane);

        // ---- coalesced f32 store ----
#pragma unroll
        for (int i = 0; i < 16; i++) {
            int p = lane + i * 32;
            int r = p >> 4, c4 = p & 15;
            long long grow = rowbase + r;
            if (grow < B)
                o4[grow * 16 + c4] = *(const float4*)(Abuf + r * AP + 16 * c4);
        }
        __syncwarp();
    }
}

// ---------------- launch ----------------
extern "C" void kernel_launch(void* const* d_in, const int* in_sizes, int n_in,
                              void* d_out, int out_size) {
    (void)n_in; (void)out_size;
    const float* x         = (const float*)d_in[0];
    const float* w_ih0     = (const float*)d_in[1];
    // d_in[2] = w_hh0      (unused: h0 == 0, T == 1)
    const float* w_ih_rest = (const float*)d_in[3];
    // d_in[4] = w_hh_rest  (unused)
    const float* b_ih      = (const float*)d_in[5];
    const float* b_hh      = (const float*)d_in[6];
    const float* fc_w      = (const float*)d_in[7];
    const float* fc_b      = (const float*)d_in[8];
    float* out = (float*)d_out;

    int B = in_sizes[0] / 64;

    _LSTM_pack<<<(40960 + 544 + 255) / 256, 256>>>(
        w_ih0, w_ih_rest, b_ih, b_hh, fc_w, fc_b);

    cudaFuncSetAttribute(_LSTM_main,
                         cudaFuncAttributeMaxDynamicSharedMemorySize, SMEM_BYTES);
    int npair = (B + 511) / 512;
    int grid = npair < GRID ? npair : GRID;
    _LSTM_main<<<grid, NT, SMEM_BYTES>>>(x, out, B);
}